// round 12
// baseline (speedup 1.0000x reference)
#include <cuda_runtime.h>
#include <cuda_fp16.h>

#define B    32
#define N    100000
#define DEG  16
#define SPB  32                  // segments per block (8 warps x 4 segs/warp)
#define NBLK (N / SPB)           // 3125, exact

// Scratch: transposed x in fp16, shape (N, 32). 6.4 MB static device array.
__device__ __half g_xT[(size_t)N * B];

__device__ __forceinline__ unsigned ucomp(const uint4& v, int j) {
    return j == 0 ? v.x : j == 1 ? v.y : j == 2 ? v.z : v.w;
}

// ---------------------------------------------------------------------------
// Kernel 1: transpose x (B=32, N) fp32 -> x_T (N, 32) fp16.
// Round-7 load phase (proven); vectorized store: each thread packs 4 halves
// and writes one uint2; warp writes 256B contiguous. Conflict-free banks.
// ---------------------------------------------------------------------------
__global__ __launch_bounds__(256) void transpose_kernel(const float* __restrict__ x,
                                                        __half* __restrict__ xT) {
    __shared__ float tile[32][33];
    const int t  = threadIdx.x;
    const int tx = t & 31;
    const int ty = t >> 5;            // 0..7
    const int n0 = blockIdx.x * 32;

    #pragma unroll
    for (int k = 0; k < 4; k++) {
        int b = ty + k * 8;
        tile[b][tx] = x[(size_t)b * N + n0 + tx];
    }
    __syncthreads();

    // Store: thread t -> xT row col = t/8, batch quad q = t%8 (8B uint2).
    // Banks: (4q+j)*33 + col -> 4q + j + col mod 32, distinct per j.
    {
        const int col = t >> 3;
        const int q   = t & 7;
        __half2 h0 = __floats2half2_rn(tile[4 * q + 0][col], tile[4 * q + 1][col]);
        __half2 h1 = __floats2half2_rn(tile[4 * q + 2][col], tile[4 * q + 3][col]);
        uint2 w = make_uint2(*reinterpret_cast<unsigned*>(&h0),
                             *reinterpret_cast<unsigned*>(&h1));
        *(uint2*)(xT + (size_t)(n0 + col) * B + 4 * q) = w;
    }
}

// ---------------------------------------------------------------------------
// Kernel 2: one warp handles FOUR segments (round-7 layout).
//   q = lane/8 owns segment; r = lane%8 handles batches 4r..4r+3 (uint2 gather).
// Uniform edge data loaded cooperatively in 2 LDG.128s
//   ld1: lanes 0-15 -> src int4 chunks (seg h/4, chunk h%4)
//        lanes 16-31 -> kern float4 chunks (same indexing, h-16)
//   ldb: all lanes -> bias chunk (lane&15)
// then redistributed via warp shuffles (ALU pipe has headroom).
// ---------------------------------------------------------------------------
__global__ __launch_bounds__(256) void pc_kernel(const float* __restrict__ kern,
                                                 const float* __restrict__ bias,
                                                 const int*   __restrict__ edge_src,
                                                 const __half* __restrict__ xT,
                                                 float*       __restrict__ out) {
    __shared__ float s_out[SPB][33];

    const int t    = threadIdx.x;
    const int warp = t >> 5;
    const int lane = t & 31;
    const int q    = lane >> 3;             // 0..3 : segment within warp
    const int r    = lane & 7;              // 0..7 : batch-quad index

    const int seg_in_blk = (warp << 2) | q; // 0..31
    const int segW = blockIdx.x * SPB + (warp << 2);
    const size_t eW = (size_t)segW * DEG;   // warp's 64 edges, 256B aligned

    // Cooperative uniform loads: 2 instructions replace 12 broadcasts.
    const uint4*  pSrc = (const uint4*) (edge_src + eW);   // 16 x int4
    const uint4*  pK   = (const uint4*) (kern + eW);       // 16 x float4
    const float4* pB   = (const float4*)(bias + eW);

    uint4  ld1 = __ldcg(lane < 16 ? &pSrc[lane] : &pK[lane - 16]);
    float4 bv  = __ldcg(&pB[lane & 15]);

    // Bias: per-chunk partial sum, gather my segment's 4 chunks via shfl.
    float psum = (bv.x + bv.y) + (bv.z + bv.w);
    float bsum = 0.0f;
    #pragma unroll
    for (int j = 0; j < 4; j++)
        bsum += __shfl_sync(0xffffffffu, psum, (q << 2) + j);

    // Src indices: 16 shfls from lanes q*4..q*4+3 (which hold src chunks).
    int s[16];
    #pragma unroll
    for (int j = 0; j < 4; j++) {
        const int hl = (q << 2) + j;
        s[4 * j + 0] = (int)__shfl_sync(0xffffffffu, ld1.x, hl);
        s[4 * j + 1] = (int)__shfl_sync(0xffffffffu, ld1.y, hl);
        s[4 * j + 2] = (int)__shfl_sync(0xffffffffu, ld1.z, hl);
        s[4 * j + 3] = (int)__shfl_sync(0xffffffffu, ld1.w, hl);
    }

    // 16 gathers, each uint2 = 4 fp16 batch elements; L2-only.
    const uint2* xt4 = (const uint2*)xT;    // xT row = 8 x uint2 (64B)
    uint2 g[16];
    #pragma unroll
    for (int d = 0; d < 16; d++)
        g[d] = __ldcg(&xt4[(size_t)s[d] * 8 + r]);

    // FMA loop; k[d] pulled by shfl from lanes 16 + q*4 + d/4 (kern holders).
    float a0 = bsum, a1 = bsum, a2 = bsum, a3 = bsum;
    #pragma unroll
    for (int d = 0; d < 16; d++) {
        unsigned kb = __shfl_sync(0xffffffffu, ucomp(ld1, d & 3),
                                  16 + (q << 2) + (d >> 2));
        float kd = __uint_as_float(kb);
        float2 lo = __half22float2(*(const __half2*)&g[d].x);
        float2 hi = __half22float2(*(const __half2*)&g[d].y);
        a0 = fmaf(lo.x, kd, a0);
        a1 = fmaf(lo.y, kd, a1);
        a2 = fmaf(hi.x, kd, a2);
        a3 = fmaf(hi.y, kd, a3);
    }

    // Stage: s_out[seg][4r..4r+3]; banks (33*seg + 4r + j) mod 32 distinct per j.
    s_out[seg_in_blk][4 * r + 0] = a0;
    s_out[seg_in_blk][4 * r + 1] = a1;
    s_out[seg_in_blk][4 * r + 2] = a2;
    s_out[seg_in_blk][4 * r + 3] = a3;
    __syncthreads();

    // Write-out: thread t -> batch row b = t/8, float4 column c = t%8.
    // out[b][n0 + 4c .. 4c+3]; 128B contiguous per batch row per block.
    const int b  = t >> 3;
    const int c  = t & 7;
    const int n0 = blockIdx.x * SPB;
    float4 v = make_float4(s_out[4 * c + 0][b], s_out[4 * c + 1][b],
                           s_out[4 * c + 2][b], s_out[4 * c + 3][b]);
    *(float4*)(out + (size_t)b * N + n0 + 4 * c) = v;
}

// ---------------------------------------------------------------------------
// d_in order: x, kernel, bias, edge_src, segment_ids, num_units
// ---------------------------------------------------------------------------
extern "C" void kernel_launch(void* const* d_in, const int* in_sizes, int n_in,
                              void* d_out, int out_size) {
    const float* x        = (const float*)d_in[0];
    const float* kern     = (const float*)d_in[1];
    const float* bias     = (const float*)d_in[2];
    const int*   edge_src = (const int*)  d_in[3];
    float*       out      = (float*)d_out;

    __half* xT;
    cudaGetSymbolAddress((void**)&xT, g_xT);

    transpose_kernel<<<N / 32, 256>>>(x, xT);
    pc_kernel<<<NBLK, 256>>>(kern, bias, edge_src, xT, out);
}

// round 13
// speedup vs baseline: 1.0296x; 1.0296x over previous
#include <cuda_runtime.h>
#include <cuda_fp16.h>

#define B    32
#define N    100000
#define DEG  16
#define SPB  32                  // segments per block (8 warps x 4 segs/warp)
#define NBLK (N / SPB)           // 3125, exact

// Scratch: transposed x in fp16, shape (N, 32). 6.4 MB static device array.
__device__ __half g_xT[(size_t)N * B];

__device__ __forceinline__ unsigned ucomp(const uint4& v, int j) {
    return j == 0 ? v.x : j == 1 ? v.y : j == 2 ? v.z : v.w;
}

// ---------------------------------------------------------------------------
// Kernel 1: transpose x (B=32, N) fp32 -> x_T (N, 32) fp16. (proven version)
// ---------------------------------------------------------------------------
__global__ __launch_bounds__(256) void transpose_kernel(const float* __restrict__ x,
                                                        __half* __restrict__ xT) {
    __shared__ float tile[32][33];
    const int t  = threadIdx.x;
    const int tx = t & 31;
    const int ty = t >> 5;            // 0..7
    const int n0 = blockIdx.x * 32;

    #pragma unroll
    for (int k = 0; k < 4; k++) {
        int b = ty + k * 8;
        tile[b][tx] = x[(size_t)b * N + n0 + tx];
    }
    __syncthreads();

    // Store: thread t -> xT row col = t/8, batch quad q = t%8 (8B uint2).
    {
        const int col = t >> 3;
        const int q   = t & 7;
        __half2 h0 = __floats2half2_rn(tile[4 * q + 0][col], tile[4 * q + 1][col]);
        __half2 h1 = __floats2half2_rn(tile[4 * q + 2][col], tile[4 * q + 3][col]);
        uint2 w = make_uint2(*reinterpret_cast<unsigned*>(&h0),
                             *reinterpret_cast<unsigned*>(&h1));
        *(uint2*)(xT + (size_t)(n0 + col) * B + 4 * q) = w;
    }
}

// ---------------------------------------------------------------------------
// Kernel 2: one warp handles FOUR segments (round-7 layout).
//   q = lane/8 owns segment; r = lane%8 handles batches 4r..4r+3 (uint2 gather).
// HYBRID uniform loads:
//   - src indices: per-segment BROADCAST int4 loads (shortest path to gathers)
//   - kern+bias:   ONE cooperative LDG.128 (lanes 0-15 kern chunks,
//                  lanes 16-31 bias chunks) + shfl, consumed after gathers
//                  are in flight (latency hidden, wavefronts saved).
// ---------------------------------------------------------------------------
__global__ __launch_bounds__(256) void pc_kernel(const float* __restrict__ kern,
                                                 const float* __restrict__ bias,
                                                 const int*   __restrict__ edge_src,
                                                 const __half* __restrict__ xT,
                                                 float*       __restrict__ out) {
    __shared__ float s_out[SPB][33];

    const int t    = threadIdx.x;
    const int warp = t >> 5;
    const int lane = t & 31;
    const int q    = lane >> 3;             // 0..3 : segment within warp
    const int r    = lane & 7;              // 0..7 : batch-quad index

    const int seg_in_blk = (warp << 2) | q; // 0..31
    const int n    = blockIdx.x * SPB + seg_in_blk;
    const size_t e0 = (size_t)n * DEG;      // my segment's 16 edges (64B)
    const int segW = blockIdx.x * SPB + (warp << 2);
    const size_t eW = (size_t)segW * DEG;   // warp's 64 edges (256B)

    // --- src: per-segment broadcast loads, issued FIRST (critical path) ---
    const int4* src4 = (const int4*)(edge_src + e0);
    int4 s0 = __ldcg(&src4[0]), s1 = __ldcg(&src4[1]),
         s2 = __ldcg(&src4[2]), s3 = __ldcg(&src4[3]);

    // --- kern+bias: one cooperative LDG.128 per warp (latency-tolerant) ---
    const uint4* pK = (const uint4*)(kern + eW);   // 16 chunks
    const uint4* pB = (const uint4*)(bias + eW);   // 16 chunks
    uint4 ld1 = __ldcg(lane < 16 ? &pK[lane] : &pB[lane - 16]);

    // --- 16 gathers, each uint2 = 4 fp16 batch elements; L2-only ---
    const uint2* xt4 = (const uint2*)xT;    // xT row = 8 x uint2 (64B)
    uint2 g[16];
    g[ 0] = __ldcg(&xt4[(size_t)s0.x * 8 + r]);
    g[ 1] = __ldcg(&xt4[(size_t)s0.y * 8 + r]);
    g[ 2] = __ldcg(&xt4[(size_t)s0.z * 8 + r]);
    g[ 3] = __ldcg(&xt4[(size_t)s0.w * 8 + r]);
    g[ 4] = __ldcg(&xt4[(size_t)s1.x * 8 + r]);
    g[ 5] = __ldcg(&xt4[(size_t)s1.y * 8 + r]);
    g[ 6] = __ldcg(&xt4[(size_t)s1.z * 8 + r]);
    g[ 7] = __ldcg(&xt4[(size_t)s1.w * 8 + r]);
    g[ 8] = __ldcg(&xt4[(size_t)s2.x * 8 + r]);
    g[ 9] = __ldcg(&xt4[(size_t)s2.y * 8 + r]);
    g[10] = __ldcg(&xt4[(size_t)s2.z * 8 + r]);
    g[11] = __ldcg(&xt4[(size_t)s2.w * 8 + r]);
    g[12] = __ldcg(&xt4[(size_t)s3.x * 8 + r]);
    g[13] = __ldcg(&xt4[(size_t)s3.y * 8 + r]);
    g[14] = __ldcg(&xt4[(size_t)s3.z * 8 + r]);
    g[15] = __ldcg(&xt4[(size_t)s3.w * 8 + r]);

    // Bias sum for my segment: lanes 16+4q..16+4q+3 hold its 4 bias chunks.
    float4 bvf = make_float4(__uint_as_float(ld1.x), __uint_as_float(ld1.y),
                             __uint_as_float(ld1.z), __uint_as_float(ld1.w));
    float psum = (bvf.x + bvf.y) + (bvf.z + bvf.w);
    float bsum = 0.0f;
    #pragma unroll
    for (int j = 0; j < 4; j++)
        bsum += __shfl_sync(0xffffffffu, psum, 16 + (q << 2) + j);

    // FMA loop; k[d] pulled by shfl from lanes q*4 + d/4 (kern holders).
    float a0 = bsum, a1 = bsum, a2 = bsum, a3 = bsum;
    #pragma unroll
    for (int d = 0; d < 16; d++) {
        unsigned kb = __shfl_sync(0xffffffffu, ucomp(ld1, d & 3),
                                  (q << 2) + (d >> 2));
        float kd = __uint_as_float(kb);
        float2 lo = __half22float2(*(const __half2*)&g[d].x);
        float2 hi = __half22float2(*(const __half2*)&g[d].y);
        a0 = fmaf(lo.x, kd, a0);
        a1 = fmaf(lo.y, kd, a1);
        a2 = fmaf(hi.x, kd, a2);
        a3 = fmaf(hi.y, kd, a3);
    }

    // Stage: s_out[seg][4r..4r+3]; banks (33*seg + 4r + j) mod 32 distinct per j.
    s_out[seg_in_blk][4 * r + 0] = a0;
    s_out[seg_in_blk][4 * r + 1] = a1;
    s_out[seg_in_blk][4 * r + 2] = a2;
    s_out[seg_in_blk][4 * r + 3] = a3;
    __syncthreads();

    // Write-out: thread t -> batch row b = t/8, float4 column c = t%8.
    // out[b][n0 + 4c .. 4c+3]; 128B contiguous per batch row per block.
    const int b  = t >> 3;
    const int c  = t & 7;
    const int n0 = blockIdx.x * SPB;
    float4 v = make_float4(s_out[4 * c + 0][b], s_out[4 * c + 1][b],
                           s_out[4 * c + 2][b], s_out[4 * c + 3][b]);
    *(float4*)(out + (size_t)b * N + n0 + 4 * c) = v;
}

// ---------------------------------------------------------------------------
// d_in order: x, kernel, bias, edge_src, segment_ids, num_units
// ---------------------------------------------------------------------------
extern "C" void kernel_launch(void* const* d_in, const int* in_sizes, int n_in,
                              void* d_out, int out_size) {
    const float* x        = (const float*)d_in[0];
    const float* kern     = (const float*)d_in[1];
    const float* bias     = (const float*)d_in[2];
    const int*   edge_src = (const int*)  d_in[3];
    float*       out      = (float*)d_out;

    __half* xT;
    cudaGetSymbolAddress((void**)&xT, g_xT);

    transpose_kernel<<<N / 32, 256>>>(x, xT);
    pc_kernel<<<NBLK, 256>>>(kern, bias, edge_src, xT, out);
}